// round 1
// baseline (speedup 1.0000x reference)
#include <cuda_runtime.h>
#include <math.h>
#include <stdint.h>

// ---------------- problem constants ----------------
#define NB 4
#define NT 1024
#define NC 768
#define NL 12
#define NH 12
#define ND 64
#define NV 10000
#define NTE 64
#define NWTE 704
#define NROWS (NB * NT)   // 4096
#define LNEPS 1e-5f

// ---------------- scratch (no allocs allowed) ----------------
__device__ float g_x[NROWS * NC];        // residual stream
__device__ float g_h[NROWS * NC];        // LN output
__device__ float g_qkv[NROWS * 3 * NC];  // qkv projection
__device__ float g_y[NROWS * NC];        // attention output
__device__ float g_mid[NROWS * 4 * NC];  // MLP hidden

// ---------------- embedding: wte gather + time encode + wpe ----------------
__global__ void embed_kernel(const int* __restrict__ idx, const float* __restrict__ ts,
                             const float* __restrict__ wte, const float* __restrict__ freq,
                             const float* __restrict__ phase, const float* __restrict__ wpe) {
    int bt = blockIdx.x;
    int t = bt & (NT - 1);
    int tok = idx[bt];
    float tv = ts[bt];
    for (int c = threadIdx.x; c < NC; c += blockDim.x) {
        float v;
        if (c < NWTE) {
            v = wte[(size_t)tok * NWTE + c];
        } else {
            int e = c - NWTE;
            v = cosf(fmaf(tv, freq[e], phase[e]));
        }
        g_x[(size_t)bt * NC + c] = v + wpe[t * NC + c];
    }
}

// ---------------- LayerNorm: one block per row, C=768 = 256*3 ----------------
__global__ __launch_bounds__(256) void ln_kernel(const float* __restrict__ in,
                                                 float* __restrict__ out,
                                                 const float* __restrict__ w,
                                                 const float* __restrict__ bb) {
    int row = blockIdx.x;
    const float* xr = in + (size_t)row * NC;
    int tid = threadIdx.x;
    float x0 = xr[tid], x1 = xr[tid + 256], x2 = xr[tid + 512];

    __shared__ float red[8];
    __shared__ float stat[2];

    float s = x0 + x1 + x2;
#pragma unroll
    for (int off = 16; off > 0; off >>= 1) s += __shfl_xor_sync(0xffffffffu, s, off);
    if ((tid & 31) == 0) red[tid >> 5] = s;
    __syncthreads();
    if (tid == 0) {
        float t = 0.f;
#pragma unroll
        for (int i = 0; i < 8; i++) t += red[i];
        stat[0] = t * (1.0f / NC);
    }
    __syncthreads();
    float mu = stat[0];
    float d0 = x0 - mu, d1 = x1 - mu, d2 = x2 - mu;
    float v = d0 * d0 + d1 * d1 + d2 * d2;
    __syncthreads();  // protect red[] reuse
#pragma unroll
    for (int off = 16; off > 0; off >>= 1) v += __shfl_xor_sync(0xffffffffu, v, off);
    if ((tid & 31) == 0) red[tid >> 5] = v;
    __syncthreads();
    if (tid == 0) {
        float t = 0.f;
#pragma unroll
        for (int i = 0; i < 8; i++) t += red[i];
        stat[1] = rsqrtf(t * (1.0f / NC) + LNEPS);
    }
    __syncthreads();
    float rstd = stat[1];
    float* orow = out + (size_t)row * NC;
    orow[tid]       = d0 * rstd * w[tid]       + bb[tid];
    orow[tid + 256] = d1 * rstd * w[tid + 256] + bb[tid + 256];
    orow[tid + 512] = d2 * rstd * w[tid + 512] + bb[tid + 512];
}

// ---------------- GEMM (NT): C[M,N] = A[M,K] @ W[N,K]^T (+bias)(+gelu)(+resid) ---
// 128x128 tile, BK=8, 256 threads, 8x8 per thread split into 2x2 4x4 quadrants.
// M multiple of 128 and K multiple of 8 guaranteed; N bounds-guarded.
template <bool HAS_BIAS, bool HAS_RESID, bool DO_GELU>
__global__ __launch_bounds__(256) void gemm_nt_kernel(
    const float* __restrict__ A, const float* __restrict__ Bw,
    const float* __restrict__ bias, const float* __restrict__ resid,
    float* __restrict__ Co, int M, int N, int K) {
    __shared__ float As[8][128];
    __shared__ float Bs[8][128];
    const int tid = threadIdx.x;
    const int bm = blockIdx.y * 128;
    const int bn = blockIdx.x * 128;
    const int lr = tid >> 1;         // 0..127 load row
    const int lk = (tid & 1) * 4;    // 0 or 4
    const int tx = tid & 15;
    const int ty = tid >> 4;

    const float* Ap = A + (size_t)(bm + lr) * K + lk;
    const int brow = bn + lr;
    const bool bok = brow < N;
    const float* Bp = Bw + (size_t)(bok ? brow : 0) * K + lk;

    float acc[2][2][4][4];
#pragma unroll
    for (int i = 0; i < 2; i++)
#pragma unroll
        for (int j = 0; j < 2; j++)
#pragma unroll
            for (int r = 0; r < 4; r++)
#pragma unroll
                for (int c = 0; c < 4; c++) acc[i][j][r][c] = 0.f;

    for (int k0 = 0; k0 < K; k0 += 8) {
        float4 a4 = *reinterpret_cast<const float4*>(Ap + k0);
        float4 b4 = bok ? *reinterpret_cast<const float4*>(Bp + k0)
                        : make_float4(0.f, 0.f, 0.f, 0.f);
        As[lk + 0][lr] = a4.x; As[lk + 1][lr] = a4.y;
        As[lk + 2][lr] = a4.z; As[lk + 3][lr] = a4.w;
        Bs[lk + 0][lr] = b4.x; Bs[lk + 1][lr] = b4.y;
        Bs[lk + 2][lr] = b4.z; Bs[lk + 3][lr] = b4.w;
        __syncthreads();
#pragma unroll
        for (int kk = 0; kk < 8; kk++) {
            float a[2][4], bfrag[2][4];
            *reinterpret_cast<float4*>(a[0])     = *reinterpret_cast<const float4*>(&As[kk][ty * 4]);
            *reinterpret_cast<float4*>(a[1])     = *reinterpret_cast<const float4*>(&As[kk][64 + ty * 4]);
            *reinterpret_cast<float4*>(bfrag[0]) = *reinterpret_cast<const float4*>(&Bs[kk][tx * 4]);
            *reinterpret_cast<float4*>(bfrag[1]) = *reinterpret_cast<const float4*>(&Bs[kk][64 + tx * 4]);
#pragma unroll
            for (int i = 0; i < 2; i++)
#pragma unroll
                for (int r = 0; r < 4; r++)
#pragma unroll
                    for (int j = 0; j < 2; j++)
#pragma unroll
                        for (int c = 0; c < 4; c++)
                            acc[i][j][r][c] = fmaf(a[i][r], bfrag[j][c], acc[i][j][r][c]);
        }
        __syncthreads();
    }

#pragma unroll
    for (int i = 0; i < 2; i++) {
#pragma unroll
        for (int r = 0; r < 4; r++) {
            int m = bm + i * 64 + ty * 4 + r;
            float* crow = Co + (size_t)m * N;
            const float* rrow = HAS_RESID ? (resid + (size_t)m * N) : nullptr;
#pragma unroll
            for (int j = 0; j < 2; j++) {
#pragma unroll
                for (int c = 0; c < 4; c++) {
                    int n = bn + j * 64 + tx * 4 + c;
                    if (n < N) {
                        float v = acc[i][j][r][c];
                        if (HAS_BIAS) v += bias[n];
                        if (DO_GELU) v = 0.5f * v * (1.f + erff(v * 0.70710678118654752f));
                        if (HAS_RESID) v += rrow[n];
                        crow[n] = v;
                    }
                }
            }
        }
    }
}

// ---------------- causal attention, flash-style online softmax ----------------
// grid (T/64, B*H), block = 64 threads; thread r owns query row (qt*64+r).
__global__ __launch_bounds__(64) void attn_kernel(const float* __restrict__ qkv,
                                                  float* __restrict__ y) {
    const int qt = blockIdx.x;
    const int bh = blockIdx.y;
    const int b = bh / NH, h = bh % NH;
    const int r = threadIdx.x;
    const int qrow = qt * 64 + r;

    const float* qp = qkv + (size_t)(b * NT + qrow) * (3 * NC) + h * ND;
    float q[ND];
#pragma unroll
    for (int d = 0; d < ND; d++) q[d] = qp[d] * 0.125f;  // 1/sqrt(64)

    float o[ND];
#pragma unroll
    for (int d = 0; d < ND; d++) o[d] = 0.f;
    float mx = -1e30f, l = 0.f;

    __shared__ float ks[64][ND + 1];
    __shared__ float vs[64][ND + 1];

    for (int kt = 0; kt <= qt; kt++) {
        __syncthreads();
        const float* kp = qkv + (size_t)(b * NT + kt * 64 + r) * (3 * NC) + NC + h * ND;
        const float* vp = kp + NC;
#pragma unroll
        for (int d = 0; d < ND; d++) { ks[r][d] = kp[d]; vs[r][d] = vp[d]; }
        __syncthreads();
        int jmax = qrow - kt * 64;
        if (jmax > 63) jmax = 63;
        for (int j = 0; j <= jmax; j++) {
            float s = 0.f;
#pragma unroll
            for (int d = 0; d < ND; d++) s = fmaf(q[d], ks[j][d], s);
            float mn = fmaxf(mx, s);
            float corr = __expf(mx - mn);
            float p = __expf(s - mn);
            l = l * corr + p;
#pragma unroll
            for (int d = 0; d < ND; d++) o[d] = fmaf(o[d], corr, p * vs[j][d]);
            mx = mn;
        }
    }
    float inv = 1.f / l;
    float* yp = y + (size_t)(b * NT + qrow) * NC + h * ND;
#pragma unroll
    for (int d = 0; d < ND; d++) yp[d] = o[d] * inv;
}

// ---------------- tpred: one warp per row dot(x, tp_w) ----------------
__global__ void tpred_kernel(const float* __restrict__ hh, const float* __restrict__ tw,
                             float* __restrict__ out) {
    int row = blockIdx.x * 8 + (threadIdx.x >> 5);
    int lane = threadIdx.x & 31;
    const float* xr = hh + (size_t)row * NC;
    float s = 0.f;
    for (int c = lane; c < NC; c += 32) s = fmaf(xr[c], tw[c], s);
#pragma unroll
    for (int off = 16; off > 0; off >>= 1) s += __shfl_xor_sync(0xffffffffu, s, off);
    if (lane == 0) out[row] = s;
}

// ---------------- orchestration ----------------
extern "C" void kernel_launch(void* const* d_in, const int* in_sizes, int n_in,
                              void* d_out, int out_size) {
    const int*   idx    = (const int*)d_in[0];
    const float* ts     = (const float*)d_in[1];
    const float* wte    = (const float*)d_in[2];
    const float* freq   = (const float*)d_in[3];
    const float* phase  = (const float*)d_in[4];
    const float* wpe    = (const float*)d_in[5];
    const float* ln1_w  = (const float*)d_in[6];
    const float* ln1_b  = (const float*)d_in[7];
    const float* qkv_w  = (const float*)d_in[8];
    const float* qkv_b  = (const float*)d_in[9];
    const float* proj_w = (const float*)d_in[10];
    const float* proj_b = (const float*)d_in[11];
    const float* ln2_w  = (const float*)d_in[12];
    const float* ln2_b  = (const float*)d_in[13];
    const float* fc_w   = (const float*)d_in[14];
    const float* fc_b   = (const float*)d_in[15];
    const float* fc2_w  = (const float*)d_in[16];
    const float* fc2_b  = (const float*)d_in[17];
    const float* lnf_w  = (const float*)d_in[18];
    const float* lnf_b  = (const float*)d_in[19];
    const float* lm_w   = (const float*)d_in[20];
    const float* tp_w   = (const float*)d_in[21];
    float* out = (float*)d_out;

    float *x, *h, *qkvb, *y, *mid;
    cudaGetSymbolAddress((void**)&x, g_x);
    cudaGetSymbolAddress((void**)&h, g_h);
    cudaGetSymbolAddress((void**)&qkvb, g_qkv);
    cudaGetSymbolAddress((void**)&y, g_y);
    cudaGetSymbolAddress((void**)&mid, g_mid);

    embed_kernel<<<NROWS, 256>>>(idx, ts, wte, freq, phase, wpe);

    for (int l = 0; l < NL; l++) {
        ln_kernel<<<NROWS, 256>>>(x, h, ln1_w + l * NC, ln1_b + l * NC);
        gemm_nt_kernel<true, false, false><<<dim3(18, 32), 256>>>(
            h, qkv_w + (size_t)l * 3 * NC * NC, qkv_b + l * 3 * NC, nullptr,
            qkvb, NROWS, 3 * NC, NC);
        attn_kernel<<<dim3(NT / 64, NB * NH), 64>>>(qkvb, y);
        gemm_nt_kernel<true, true, false><<<dim3(6, 32), 256>>>(
            y, proj_w + (size_t)l * NC * NC, proj_b + l * NC, x,
            x, NROWS, NC, NC);
        ln_kernel<<<NROWS, 256>>>(x, h, ln2_w + l * NC, ln2_b + l * NC);
        gemm_nt_kernel<true, false, true><<<dim3(24, 32), 256>>>(
            h, fc_w + (size_t)l * 4 * NC * NC, fc_b + l * 4 * NC, nullptr,
            mid, NROWS, 4 * NC, NC);
        gemm_nt_kernel<true, true, false><<<dim3(6, 32), 256>>>(
            mid, fc2_w + (size_t)l * NC * 4 * NC, fc2_b + l * NC, x,
            x, NROWS, NC, 4 * NC);
    }

    ln_kernel<<<NROWS, 256>>>(x, h, lnf_w, lnf_b);
    gemm_nt_kernel<false, false, false><<<dim3((NV + 127) / 128, 32), 256>>>(
        h, lm_w, nullptr, nullptr, out, NROWS, NV, NC);
    tpred_kernel<<<NROWS / 8, 256>>>(h, tp_w, out + (size_t)NROWS * NV);
}

// round 3
// speedup vs baseline: 1.4440x; 1.4440x over previous
#include <cuda_runtime.h>
#include <math.h>
#include <stdint.h>

// ---------------- problem constants ----------------
#define NB 4
#define NT 1024
#define NC 768
#define NL 12
#define NH 12
#define ND 64
#define NV 10000
#define NTE 64
#define NWTE 704
#define NROWS (NB * NT)   // 4096
#define LNEPS 1e-5f

// ---------------- scratch (no allocs allowed) ----------------
__device__ float g_x[NROWS * NC];        // residual stream
__device__ float g_h[NROWS * NC];        // LN output
__device__ float g_qkv[NROWS * 3 * NC];  // qkv projection
__device__ float g_y[NROWS * NC];        // attention output
__device__ float g_mid[NROWS * 4 * NC];  // MLP hidden

// ---------------- async copy helpers ----------------
__device__ __forceinline__ void cp_async16(void* smem, const void* gmem) {
    unsigned s = (unsigned)__cvta_generic_to_shared(smem);
    asm volatile("cp.async.cg.shared.global [%0], [%1], 16;" :: "r"(s), "l"(gmem));
}
__device__ __forceinline__ void cp_commit() { asm volatile("cp.async.commit_group;"); }
template <int N>
__device__ __forceinline__ void cp_wait() { asm volatile("cp.async.wait_group %0;" :: "n"(N)); }

// tf32 split: x ~= hi + lo, both representable in tf32 (rna rounding)
__device__ __forceinline__ void tf32_split(float x, unsigned& hi, unsigned& lo) {
    asm("cvt.rna.tf32.f32 %0, %1;" : "=r"(hi) : "f"(x));
    float r = __fsub_rn(x, __uint_as_float(hi));
    asm("cvt.rna.tf32.f32 %0, %1;" : "=r"(lo) : "f"(r));
}

__device__ __forceinline__ void mma_tf32(float* c, const unsigned* a, const unsigned* b) {
    asm volatile(
        "mma.sync.aligned.m16n8k8.row.col.f32.tf32.tf32.f32 "
        "{%0,%1,%2,%3}, {%4,%5,%6,%7}, {%8,%9}, {%0,%1,%2,%3};"
        : "+f"(c[0]), "+f"(c[1]), "+f"(c[2]), "+f"(c[3])
        : "r"(a[0]), "r"(a[1]), "r"(a[2]), "r"(a[3]), "r"(b[0]), "r"(b[1]));
}

// ---------------- embedding: wte gather + time encode + wpe ----------------
__global__ void embed_kernel(const int* __restrict__ idx, const float* __restrict__ ts,
                             const float* __restrict__ wte, const float* __restrict__ freq,
                             const float* __restrict__ phase, const float* __restrict__ wpe) {
    int bt = blockIdx.x;
    int t = bt & (NT - 1);
    int tok = idx[bt];
    float tv = ts[bt];
    for (int c = threadIdx.x; c < NC; c += blockDim.x) {
        float v;
        if (c < NWTE) {
            v = wte[(size_t)tok * NWTE + c];
        } else {
            int e = c - NWTE;
            v = cosf(fmaf(tv, freq[e], phase[e]));
        }
        g_x[(size_t)bt * NC + c] = v + wpe[t * NC + c];
    }
}

// ---------------- LayerNorm: one block per row ----------------
__global__ __launch_bounds__(256) void ln_kernel(const float* __restrict__ in,
                                                 float* __restrict__ out,
                                                 const float* __restrict__ w,
                                                 const float* __restrict__ bb) {
    int row = blockIdx.x;
    const float* xr = in + (size_t)row * NC;
    int tid = threadIdx.x;
    float x0 = xr[tid], x1 = xr[tid + 256], x2 = xr[tid + 512];

    __shared__ float red[8];
    __shared__ float stat[2];

    float s = x0 + x1 + x2;
#pragma unroll
    for (int off = 16; off > 0; off >>= 1) s += __shfl_xor_sync(0xffffffffu, s, off);
    if ((tid & 31) == 0) red[tid >> 5] = s;
    __syncthreads();
    if (tid == 0) {
        float t = 0.f;
#pragma unroll
        for (int i = 0; i < 8; i++) t += red[i];
        stat[0] = t * (1.0f / NC);
    }
    __syncthreads();
    float mu = stat[0];
    float d0 = x0 - mu, d1 = x1 - mu, d2 = x2 - mu;
    float v = d0 * d0 + d1 * d1 + d2 * d2;
    __syncthreads();
#pragma unroll
    for (int off = 16; off > 0; off >>= 1) v += __shfl_xor_sync(0xffffffffu, v, off);
    if ((tid & 31) == 0) red[tid >> 5] = v;
    __syncthreads();
    if (tid == 0) {
        float t = 0.f;
#pragma unroll
        for (int i = 0; i < 8; i++) t += red[i];
        stat[1] = rsqrtf(t * (1.0f / NC) + LNEPS);
    }
    __syncthreads();
    float rstd = stat[1];
    float* orow = out + (size_t)row * NC;
    orow[tid]       = d0 * rstd * w[tid]       + bb[tid];
    orow[tid + 256] = d1 * rstd * w[tid + 256] + bb[tid + 256];
    orow[tid + 512] = d2 * rstd * w[tid + 512] + bb[tid + 512];
}

// ---------------- tf32 tensor-core GEMM (NT): C = A[M,K] @ W[N,K]^T ----------
// 128x128 tile, BK=16, 256 threads (8 warps 2x4), warp tile 64x32.
// 3xTF32 (hi/lo split) for fp32-class accuracy. cp.async double buffer.
template <bool HAS_BIAS, bool HAS_RESID, bool DO_GELU>
__global__ __launch_bounds__(256) void gemm_tc_kernel(
    const float* __restrict__ A, const float* __restrict__ Bw,
    const float* __restrict__ bias, const float* __restrict__ resid,
    float* __restrict__ Co, int M, int N, int K) {
    __shared__ float As[2][128][20];
    __shared__ float Bs[2][128][20];

    const int tid = threadIdx.x;
    const int bm = blockIdx.y * 128;
    const int bn = blockIdx.x * 128;
    const int warp = tid >> 5, lane = tid & 31;
    const int wm = warp >> 2, wn = warp & 3;
    const int gid = lane >> 2, ctg = lane & 3;
    const int lr = tid >> 1, lc = (tid & 1) * 8;

    const float* Ag = A + (size_t)(bm + lr) * K + lc;
    int brow = bn + lr;
    if (brow >= N) brow = N - 1;
    const float* Bg = Bw + (size_t)brow * K + lc;

    float acc[4][4][4];
#pragma unroll
    for (int i = 0; i < 4; i++)
#pragma unroll
        for (int j = 0; j < 4; j++)
#pragma unroll
            for (int r = 0; r < 4; r++) acc[i][j][r] = 0.f;

    const int nk = K >> 4;
    cp_async16(&As[0][lr][lc], Ag);
    cp_async16(&As[0][lr][lc + 4], Ag + 4);
    cp_async16(&Bs[0][lr][lc], Bg);
    cp_async16(&Bs[0][lr][lc + 4], Bg + 4);
    cp_commit();

    for (int i = 0; i < nk; i++) {
        if (i + 1 < nk) {
            int st = (i + 1) & 1, k0 = (i + 1) * 16;
            cp_async16(&As[st][lr][lc], Ag + k0);
            cp_async16(&As[st][lr][lc + 4], Ag + k0 + 4);
            cp_async16(&Bs[st][lr][lc], Bg + k0);
            cp_async16(&Bs[st][lr][lc + 4], Bg + k0 + 4);
        }
        cp_commit();
        cp_wait<1>();
        __syncthreads();
        const int st = i & 1;
#pragma unroll
        for (int kk = 0; kk < 16; kk += 8) {
            unsigned Ah[4][4], Al[4][4], Bh[4][2], Bl[4][2];
            const int c0 = kk + ctg, c1 = kk + ctg + 4;
#pragma unroll
            for (int tm = 0; tm < 4; tm++) {
                int r0 = wm * 64 + tm * 16 + gid;
                tf32_split(As[st][r0][c0],     Ah[tm][0], Al[tm][0]);
                tf32_split(As[st][r0 + 8][c0], Ah[tm][1], Al[tm][1]);
                tf32_split(As[st][r0][c1],     Ah[tm][2], Al[tm][2]);
                tf32_split(As[st][r0 + 8][c1], Ah[tm][3], Al[tm][3]);
            }
#pragma unroll
            for (int tn = 0; tn < 4; tn++) {
                int n0 = wn * 32 + tn * 8 + gid;
                tf32_split(Bs[st][n0][c0], Bh[tn][0], Bl[tn][0]);
                tf32_split(Bs[st][n0][c1], Bh[tn][1], Bl[tn][1]);
            }
#pragma unroll
            for (int tm = 0; tm < 4; tm++)
#pragma unroll
                for (int tn = 0; tn < 4; tn++) {
                    mma_tf32(acc[tm][tn], Ah[tm], Bl[tn]);
                    mma_tf32(acc[tm][tn], Al[tm], Bh[tn]);
                    mma_tf32(acc[tm][tn], Ah[tm], Bh[tn]);
                }
        }
        __syncthreads();
    }

    // epilogue: each thread owns rows (gid, gid+8), cols 2*ctg..2*ctg+1 per tile
#pragma unroll
    for (int tm = 0; tm < 4; tm++) {
#pragma unroll
        for (int half = 0; half < 2; half++) {
            int m = bm + wm * 64 + tm * 16 + gid + half * 8;
            float* crow = Co + (size_t)m * N;
            const float* rrow = HAS_RESID ? (resid + (size_t)m * N) : nullptr;
#pragma unroll
            for (int tn = 0; tn < 4; tn++) {
                int n = bn + wn * 32 + tn * 8 + 2 * ctg;
                if (n < N) {  // N even, n even -> covers n+1 too
                    float v0 = acc[tm][tn][half * 2 + 0];
                    float v1 = acc[tm][tn][half * 2 + 1];
                    if (HAS_BIAS) { v0 += bias[n]; v1 += bias[n + 1]; }
                    if (DO_GELU) {
                        v0 = 0.5f * v0 * (1.f + erff(v0 * 0.70710678118654752f));
                        v1 = 0.5f * v1 * (1.f + erff(v1 * 0.70710678118654752f));
                    }
                    if (HAS_RESID) { v0 += rrow[n]; v1 += rrow[n + 1]; }
                    *reinterpret_cast<float2*>(crow + n) = make_float2(v0, v1);
                }
            }
        }
    }
}

// ---------------- causal attention, flash-style online softmax ----------------
// grid (T/128, B*H), block = 128 threads; thread r owns query row (qt*128+r).
__global__ __launch_bounds__(128) void attn_kernel(const float* __restrict__ qkv,
                                                   float* __restrict__ y) {
    const int qt = blockIdx.x;
    const int bh = blockIdx.y;
    const int b = bh / NH, h = bh % NH;
    const int r = threadIdx.x;
    const int qrow = qt * 128 + r;

    const float* qp = qkv + (size_t)(b * NT + qrow) * (3 * NC) + h * ND;
    float q[ND];
#pragma unroll
    for (int d = 0; d < ND; d++) q[d] = qp[d] * 0.125f;  // 1/sqrt(64)

    float o[ND];
#pragma unroll
    for (int d = 0; d < ND; d++) o[d] = 0.f;
    float mx = -1e30f, l = 0.f;

    __shared__ float ks[64][68];
    __shared__ float vs[64][68];

    const int ntile = 2 * (qt + 1);
    for (int kt = 0; kt < ntile; kt++) {
        __syncthreads();
        {
            int j = r >> 1;
            int half = (r & 1) * 32;
            const float* kp = qkv + (size_t)(b * NT + kt * 64 + j) * (3 * NC) + NC + h * ND + half;
            const float* vp = kp + NC;
#pragma unroll
            for (int d = 0; d < 32; d += 4) {
                *reinterpret_cast<float4*>(&ks[j][half + d]) = *reinterpret_cast<const float4*>(kp + d);
                *reinterpret_cast<float4*>(&vs[j][half + d]) = *reinterpret_cast<const float4*>(vp + d);
            }
        }
        __syncthreads();
        int jmax = qrow - kt * 64;
        if (jmax < 0) continue;
        if (jmax > 63) jmax = 63;
        for (int j = 0; j <= jmax; j++) {
            float s = 0.f;
#pragma unroll
            for (int d = 0; d < ND; d++) s = fmaf(q[d], ks[j][d], s);
            float mn = fmaxf(mx, s);
            float corr = __expf(mx - mn);
            float p = __expf(s - mn);
            l = l * corr + p;
#pragma unroll
            for (int d = 0; d < ND; d++) o[d] = fmaf(o[d], corr, p * vs[j][d]);
            mx = mn;
        }
    }
    float inv = 1.f / l;
    float* yp = y + (size_t)(b * NT + qrow) * NC + h * ND;
#pragma unroll
    for (int d = 0; d < ND; d++) yp[d] = o[d] * inv;
}

// ---------------- tpred: one warp per row dot(x, tp_w) ----------------
__global__ void tpred_kernel(const float* __restrict__ hh, const float* __restrict__ tw,
                             float* __restrict__ out) {
    int row = blockIdx.x * 8 + (threadIdx.x >> 5);
    int lane = threadIdx.x & 31;
    const float* xr = hh + (size_t)row * NC;
    float s = 0.f;
    for (int c = lane; c < NC; c += 32) s = fmaf(xr[c], tw[c], s);
#pragma unroll
    for (int off = 16; off > 0; off >>= 1) s += __shfl_xor_sync(0xffffffffu, s, off);
    if (lane == 0) out[row] = s;
}

// ---------------- orchestration ----------------
extern "C" void kernel_launch(void* const* d_in, const int* in_sizes, int n_in,
                              void* d_out, int out_size) {
    const int*   idx    = (const int*)d_in[0];
    const float* ts     = (const float*)d_in[1];
    const float* wte    = (const float*)d_in[2];
    const float* freq   = (const float*)d_in[3];
    const float* phase  = (const float*)d_in[4];
    const float* wpe    = (const float*)d_in[5];
    const float* ln1_w  = (const float*)d_in[6];
    const float* ln1_b  = (const float*)d_in[7];
    const float* qkv_w  = (const float*)d_in[8];
    const float* qkv_b  = (const float*)d_in[9];
    const float* proj_w = (const float*)d_in[10];
    const float* proj_b = (const float*)d_in[11];
    const float* ln2_w  = (const float*)d_in[12];
    const float* ln2_b  = (const float*)d_in[13];
    const float* fc_w   = (const float*)d_in[14];
    const float* fc_b   = (const float*)d_in[15];
    const float* fc2_w  = (const float*)d_in[16];
    const float* fc2_b  = (const float*)d_in[17];
    const float* lnf_w  = (const float*)d_in[18];
    const float* lnf_b  = (const float*)d_in[19];
    const float* lm_w   = (const float*)d_in[20];
    const float* tp_w   = (const float*)d_in[21];
    float* out = (float*)d_out;

    float *x, *h, *qkvb, *y, *mid;
    cudaGetSymbolAddress((void**)&x, g_x);
    cudaGetSymbolAddress((void**)&h, g_h);
    cudaGetSymbolAddress((void**)&qkvb, g_qkv);
    cudaGetSymbolAddress((void**)&y, g_y);
    cudaGetSymbolAddress((void**)&mid, g_mid);

    embed_kernel<<<NROWS, 256>>>(idx, ts, wte, freq, phase, wpe);

    for (int l = 0; l < NL; l++) {
        ln_kernel<<<NROWS, 256>>>(x, h, ln1_w + l * NC, ln1_b + l * NC);
        gemm_tc_kernel<true, false, false><<<dim3(18, 32), 256>>>(
            h, qkv_w + (size_t)l * 3 * NC * NC, qkv_b + l * 3 * NC, nullptr,
            qkvb, NROWS, 3 * NC, NC);
        attn_kernel<<<dim3(NT / 128, NB * NH), 128>>>(qkvb, y);
        gemm_tc_kernel<true, true, false><<<dim3(6, 32), 256>>>(
            y, proj_w + (size_t)l * NC * NC, proj_b + l * NC, x,
            x, NROWS, NC, NC);
        ln_kernel<<<NROWS, 256>>>(x, h, ln2_w + l * NC, ln2_b + l * NC);
        gemm_tc_kernel<true, false, true><<<dim3(24, 32), 256>>>(
            h, fc_w + (size_t)l * 4 * NC * NC, fc_b + l * 4 * NC, nullptr,
            mid, NROWS, 4 * NC, NC);
        gemm_tc_kernel<true, true, false><<<dim3(6, 32), 256>>>(
            mid, fc2_w + (size_t)l * NC * 4 * NC, fc2_b + l * NC, x,
            x, NROWS, NC, 4 * NC);
    }

    ln_kernel<<<NROWS, 256>>>(x, h, lnf_w, lnf_b);
    gemm_tc_kernel<false, false, false><<<dim3((NV + 127) / 128, 32), 256>>>(
        h, lm_w, nullptr, nullptr, out, NROWS, NV, NC);
    tpred_kernel<<<NROWS / 8, 256>>>(h, tp_w, out + (size_t)NROWS * NV);
}